// round 7
// baseline (speedup 1.0000x reference)
#include <cuda_runtime.h>
#include <cuda_fp16.h>
#include <cstdint>

#define NN   100000
#define EE   3200000
#define INC  128
#define HID  64
#define OUTC 16

// ---------------- scratch (static device globals; no allocation) -------------
__device__ __half2 g_h0h[NN * 32];    // (x @ W1) * dis[row], fp16, 64ch (32 half2)
__device__ __half2 g_zh[NN * 16];     // (relu(agg1) @ [Wmu|Wls]) * dis[row], 32ch
__device__ float g_dis[NN];           // (deg+1)^-1/2
__device__ int   g_src[EE];
__device__ int   g_dst[EE];
__device__ int   g_csr[EE];           // src indices sorted by dst
__device__ int   g_degi[NN];
__device__ int   g_offA[NN];
__device__ int   g_off[NN];
__device__ int   g_woff[NN];
__device__ int   g_bsum[1024];
__device__ int   g_bpre[1024];
__device__ int   g_is64;

// ---------------- dtype detection + index conversion + degree count ----------
__global__ void k_detect(const int* e) {
    int all_zero = 1;
    #pragma unroll
    for (int i = 1; i < 129; i += 2)
        if (e[i] != 0) { all_zero = 0; break; }
    g_is64 = all_zero;
}

__global__ void k_zero_deg(int n) {
    int i = blockIdx.x * blockDim.x + threadIdx.x;
    if (i < n) g_degi[i] = 0;
}

__global__ void k_conv_count(const void* eidx, int E) {
    int i = blockIdx.x * blockDim.x + threadIdx.x;
    if (i >= 2 * E) return;
    int v;
    if (g_is64) v = (int)((const long long*)eidx)[i];
    else        v = ((const int*)eidx)[i];
    if (i < E) {
        g_src[i] = v;
    } else {
        g_dst[i - E] = v;
        atomicAdd(&g_degi[v], 1);
    }
}

// ---------------- hierarchical exclusive scan of degrees ---------------------
__global__ void k_scan1(int n) {
    __shared__ int s[256];
    int i = blockIdx.x * 256 + threadIdx.x;
    int v = (i < n) ? g_degi[i] : 0;
    s[threadIdx.x] = v;
    __syncthreads();
    #pragma unroll
    for (int off = 1; off < 256; off <<= 1) {
        int t = (threadIdx.x >= off) ? s[threadIdx.x - off] : 0;
        __syncthreads();
        s[threadIdx.x] += t;
        __syncthreads();
    }
    if (i < n) g_offA[i] = s[threadIdx.x] - v;
    if (threadIdx.x == 255) g_bsum[blockIdx.x] = s[255];
}

__global__ void k_scan2(int nb) {
    __shared__ int s[1024];
    int v = (threadIdx.x < nb) ? g_bsum[threadIdx.x] : 0;
    s[threadIdx.x] = v;
    __syncthreads();
    #pragma unroll
    for (int off = 1; off < 1024; off <<= 1) {
        int t = (threadIdx.x >= off) ? s[threadIdx.x - off] : 0;
        __syncthreads();
        s[threadIdx.x] += t;
        __syncthreads();
    }
    if (threadIdx.x < nb) g_bpre[threadIdx.x] = s[threadIdx.x] - v;
}

__global__ void k_scan3(int n) {
    int i = blockIdx.x * blockDim.x + threadIdx.x;
    if (i >= n) return;
    int o = g_offA[i] + g_bpre[i >> 8];
    g_off[i]  = o;
    g_woff[i] = o;
    g_dis[i]  = rsqrtf((float)(g_degi[i] + 1));
}

// ---------------- counting-sort scatter: CSR of src by dst -------------------
__global__ void k_scatter(int E) {
    int e = blockIdx.x * blockDim.x + threadIdx.x;
    if (e >= E) return;
    int d = g_dst[e];
    int pos = atomicAdd(&g_woff[d], 1);
    g_csr[pos] = g_src[e];
}

// ---------------- GEMM1: h0h = fp16( (x @ W1) * dis[row] ) -------------------
__global__ __launch_bounds__(256) void k_gemm1(const float* __restrict__ x,
                                               const float* __restrict__ W,
                                               int n) {
    __shared__ float Ws[INC][HID];    // 32 KB
    __shared__ float xs[16][INC];     // 8 KB
    int tx = threadIdx.x, ty = threadIdx.y;          // blockDim (16,16)
    int tid = ty * 16 + tx;
    for (int i = tid; i < INC * HID; i += 256)
        ((float*)Ws)[i] = W[i];
    int row0 = blockIdx.x * 16;
    for (int i = tid; i < 16 * INC; i += 256) {
        int r = i >> 7, k = i & 127;
        int row = row0 + r;
        xs[r][k] = (row < n) ? x[row * INC + k] : 0.f;
    }
    __syncthreads();

    float4 acc = make_float4(0.f, 0.f, 0.f, 0.f);
    #pragma unroll 8
    for (int k = 0; k < INC; k++) {
        float xv = xs[ty][k];
        float4 w = *(const float4*)&Ws[k][tx * 4];
        acc.x += xv * w.x; acc.y += xv * w.y;
        acc.z += xv * w.z; acc.w += xv * w.w;
    }
    int row = row0 + ty;
    if (row < n) {
        float d = g_dis[row];                    // pre-scale by dis[src]
        __half2 h01 = __floats2half2_rn(acc.x * d, acc.y * d);
        __half2 h23 = __floats2half2_rn(acc.z * d, acc.w * d);
        g_h0h[row * 32 + tx * 2]     = h01;
        g_h0h[row * 32 + tx * 2 + 1] = h23;
    }
}

// ---------------- fused layer-1 aggregation + GEMM2 --------------------------
// One warp per node (32 thr, half2 = 64 ch). Then in-block 64x32 projection:
//   zs[node] = ( relu( dis[node]*(h0s[node] + sum h0s[src]) + b1 ) @ Wc ) * dis
__global__ __launch_bounds__(256) void k_agg64_gemm2(const float* __restrict__ b1,
                                                     const float* __restrict__ Wmu,
                                                     const float* __restrict__ Wls,
                                                     int n) {
    __shared__ float hs[8][HID];     // 2 KB
    __shared__ float Wc[HID][32];    // 8 KB: cols 0..15 = W_mu, 16..31 = W_ls
    int tid  = threadIdx.x;
    int warp = tid >> 5, lane = tid & 31;
    for (int i = tid; i < HID * OUTC; i += 256) {
        int k = i >> 4, c = i & 15;
        Wc[k][c]      = Wmu[i];
        Wc[k][16 + c] = Wls[i];
    }
    int node = blockIdx.x * 8 + warp;
    if (node < n) {
        float2 acc = __half22float2(g_h0h[node * 32 + lane]);  // self (pre-scaled)
        int k   = g_off[node];
        int end = k + g_degi[node];
        for (; k + 3 < end; k += 4) {
            int s0 = g_csr[k],     s1 = g_csr[k + 1];
            int s2 = g_csr[k + 2], s3 = g_csr[k + 3];
            float2 a0 = __half22float2(g_h0h[s0 * 32 + lane]);
            float2 a1 = __half22float2(g_h0h[s1 * 32 + lane]);
            float2 a2 = __half22float2(g_h0h[s2 * 32 + lane]);
            float2 a3 = __half22float2(g_h0h[s3 * 32 + lane]);
            acc.x += a0.x + a1.x + a2.x + a3.x;
            acc.y += a0.y + a1.y + a2.y + a3.y;
        }
        for (; k < end; k++) {
            float2 a0 = __half22float2(g_h0h[g_csr[k] * 32 + lane]);
            acc.x += a0.x; acc.y += a0.y;
        }
        float d = g_dis[node];
        int c2 = lane * 2;
        float2 bb = *(const float2*)&b1[c2];
        hs[warp][c2]     = fmaxf(acc.x * d + bb.x, 0.f);
        hs[warp][c2 + 1] = fmaxf(acc.y * d + bb.y, 0.f);
    }
    __syncthreads();
    // projection: warp w computes 32 output cols of its node; pack pairs to half2
    if (node < n) {
        float s0 = 0.f, s1 = 0.f;
        #pragma unroll
        for (int k = 0; k < HID; k++) {
            float hv = hs[warp][k];
            s0 += hv * Wc[k][(lane & 15) * 2];
            s1 += hv * Wc[k][(lane & 15) * 2 + 1];
        }
        // lanes 0..15 compute col pairs 0..31; lanes 16..31 duplicate — keep
        // only lanes 0..15 as writers to avoid double stores
        if (lane < 16) {
            float d = g_dis[node];
            g_zh[node * 16 + lane] = __floats2half2_rn(s0 * d, s1 * d);
        }
    }
}

// ---------------- layer-2 aggregation (16-lane subwarp/node, half2/lane) -----
// out layout: [0 .. n*16) = mu, [n*16 .. n*32) = logstd
__global__ __launch_bounds__(256) void k_agg32(const float* __restrict__ bmu,
                                               const float* __restrict__ bls,
                                               float* __restrict__ out, int n) {
    int tid  = threadIdx.x;
    int node = blockIdx.x * 16 + (tid >> 4);     // 2 nodes per warp
    if (node >= n) return;
    int li = tid & 15;                            // lane within sub-warp
    float2 acc = __half22float2(g_zh[node * 16 + li]);   // self (pre-scaled)
    int k   = g_off[node];
    int end = k + g_degi[node];
    for (; k + 3 < end; k += 4) {
        int s0 = g_csr[k],     s1 = g_csr[k + 1];
        int s2 = g_csr[k + 2], s3 = g_csr[k + 3];
        float2 a0 = __half22float2(g_zh[s0 * 16 + li]);
        float2 a1 = __half22float2(g_zh[s1 * 16 + li]);
        float2 a2 = __half22float2(g_zh[s2 * 16 + li]);
        float2 a3 = __half22float2(g_zh[s3 * 16 + li]);
        acc.x += a0.x + a1.x + a2.x + a3.x;
        acc.y += a0.y + a1.y + a2.y + a3.y;
    }
    for (; k < end; k++) {
        float2 a0 = __half22float2(g_zh[g_csr[k] * 16 + li]);
        acc.x += a0.x; acc.y += a0.y;
    }
    float d = g_dis[node];
    int c2 = li * 2;                              // channel pair [0..31)
    float2 r;
    if (c2 < 16) {
        const float2 bb = *(const float2*)&bmu[c2];
        r.x = acc.x * d + bb.x; r.y = acc.y * d + bb.y;
        *(float2*)&out[node * 16 + c2] = r;
    } else {
        const float2 bb = *(const float2*)&bls[c2 - 16];
        r.x = acc.x * d + bb.x; r.y = acc.y * d + bb.y;
        *(float2*)&out[n * 16 + node * 16 + (c2 - 16)] = r;
    }
}

// ---------------- launch ------------------------------------------------------
extern "C" void kernel_launch(void* const* d_in, const int* in_sizes, int n_in,
                              void* d_out, int out_size) {
    const float* x   = (const float*)d_in[0];
    const void*  eix = d_in[1];
    const float* W1  = (const float*)d_in[2];
    const float* b1  = (const float*)d_in[3];
    const float* Wmu = (const float*)d_in[4];
    const float* bmu = (const float*)d_in[5];
    const float* Wls = (const float*)d_in[6];
    const float* bls = (const float*)d_in[7];
    float* out = (float*)d_out;

    int n = in_sizes[0] / INC;      // 100000
    int E = in_sizes[1] / 2;        // 3200000
    int nb = (n + 255) / 256;

    k_detect<<<1, 1>>>((const int*)eix);
    k_zero_deg<<<nb, 256>>>(n);
    k_conv_count<<<(2 * E + 255) / 256, 256>>>(eix, E);

    k_scan1<<<nb, 256>>>(n);
    k_scan2<<<1, 1024>>>(nb);
    k_scan3<<<nb, 256>>>(n);
    k_scatter<<<(E + 255) / 256, 256>>>(E);

    k_gemm1<<<(n + 15) / 16, dim3(16, 16)>>>(x, W1, n);
    k_agg64_gemm2<<<(n + 7) / 8, 256>>>(b1, Wmu, Wls, n);
    k_agg32<<<(n + 15) / 16, 256>>>(bmu, bls, out, n);
}

// round 8
// speedup vs baseline: 1.1329x; 1.1329x over previous
#include <cuda_runtime.h>
#include <cuda_fp16.h>
#include <cstdint>

#define NN   100000
#define EE   3200000
#define INC  128
#define HID  64
#define OUTC 16

// ---------------- scratch (static device globals; no allocation) -------------
__device__ __half2 g_h0h[NN * 32];    // (x @ W1) * dis[row], fp16, 64ch (32 half2)
__device__ __half2 g_zh[NN * 16];     // (relu(agg1) @ [Wmu|Wls]) * dis[row], 32ch
__device__ float g_dis[NN];           // (deg+1)^-1/2
__device__ int   g_dst[EE];
__device__ int   g_csr[EE];           // src indices sorted by dst
__device__ int   g_degi[NN];
__device__ int   g_offA[NN];
__device__ int   g_off[NN];
__device__ int   g_woff[NN];
__device__ int   g_bsum[1024];
__device__ int   g_bpre[1024];
__device__ int   g_is64;

// ---------------- dtype detection -------------------------------------------
__global__ void k_detect(const int* e) {
    int all_zero = 1;
    #pragma unroll
    for (int i = 1; i < 129; i += 2)
        if (e[i] != 0) { all_zero = 0; break; }
    g_is64 = all_zero;
}

__global__ void k_zero_deg(int n) {
    int i = blockIdx.x * blockDim.x + threadIdx.x;
    if (i < n) g_degi[i] = 0;
}

// convert ONLY the dst half + count in-degree
__global__ void k_conv_count(const void* eidx, int E) {
    int i = blockIdx.x * blockDim.x + threadIdx.x;
    if (i >= E) return;
    int v;
    if (g_is64) v = (int)((const long long*)eidx)[E + i];
    else        v = ((const int*)eidx)[E + i];
    g_dst[i] = v;
    atomicAdd(&g_degi[v], 1);
}

// ---------------- hierarchical exclusive scan of degrees ---------------------
__global__ void k_scan1(int n) {
    __shared__ int s[256];
    int i = blockIdx.x * 256 + threadIdx.x;
    int v = (i < n) ? g_degi[i] : 0;
    s[threadIdx.x] = v;
    __syncthreads();
    #pragma unroll
    for (int off = 1; off < 256; off <<= 1) {
        int t = (threadIdx.x >= off) ? s[threadIdx.x - off] : 0;
        __syncthreads();
        s[threadIdx.x] += t;
        __syncthreads();
    }
    if (i < n) g_offA[i] = s[threadIdx.x] - v;
    if (threadIdx.x == 255) g_bsum[blockIdx.x] = s[255];
}

__global__ void k_scan2(int nb) {
    __shared__ int s[1024];
    int v = (threadIdx.x < nb) ? g_bsum[threadIdx.x] : 0;
    s[threadIdx.x] = v;
    __syncthreads();
    #pragma unroll
    for (int off = 1; off < 1024; off <<= 1) {
        int t = (threadIdx.x >= off) ? s[threadIdx.x - off] : 0;
        __syncthreads();
        s[threadIdx.x] += t;
        __syncthreads();
    }
    if (threadIdx.x < nb) g_bpre[threadIdx.x] = s[threadIdx.x] - v;
}

__global__ void k_scan3(int n) {
    int i = blockIdx.x * blockDim.x + threadIdx.x;
    if (i >= n) return;
    int o = g_offA[i] + g_bpre[i >> 8];
    g_off[i]  = o;
    g_woff[i] = o;
    g_dis[i]  = rsqrtf((float)(g_degi[i] + 1));
}

// ---------------- counting-sort scatter (converts src inline) ----------------
__global__ void k_scatter(const void* eidx, int E) {
    int e = blockIdx.x * blockDim.x + threadIdx.x;
    if (e >= E) return;
    int d = g_dst[e];
    int pos = atomicAdd(&g_woff[d], 1);
    int s;
    if (g_is64) s = (int)((const long long*)eidx)[e];
    else        s = ((const int*)eidx)[e];
    g_csr[pos] = s;
}

// ---------------- GEMM1: h0h = fp16( (x @ W1) * dis[row] ), 2 rows/thread ----
__global__ __launch_bounds__(256) void k_gemm1(const float* __restrict__ x,
                                               const float* __restrict__ W,
                                               int n) {
    __shared__ float Ws[INC][HID];    // 32 KB
    __shared__ float xs[32][INC];     // 16 KB
    int tx = threadIdx.x, ty = threadIdx.y;          // blockDim (16,16)
    int tid = ty * 16 + tx;
    for (int i = tid; i < INC * HID; i += 256)
        ((float*)Ws)[i] = W[i];
    int row0 = blockIdx.x * 32;
    for (int i = tid; i < 32 * INC; i += 256) {
        int r = i >> 7, k = i & 127;
        int row = row0 + r;
        xs[r][k] = (row < n) ? x[row * INC + k] : 0.f;
    }
    __syncthreads();

    float4 a0 = make_float4(0.f, 0.f, 0.f, 0.f);
    float4 a1 = make_float4(0.f, 0.f, 0.f, 0.f);
    #pragma unroll 4
    for (int k = 0; k < INC; k++) {
        float4 w = *(const float4*)&Ws[k][tx * 4];
        float v0 = xs[ty][k];
        float v1 = xs[ty + 16][k];
        a0.x += v0 * w.x; a0.y += v0 * w.y; a0.z += v0 * w.z; a0.w += v0 * w.w;
        a1.x += v1 * w.x; a1.y += v1 * w.y; a1.z += v1 * w.z; a1.w += v1 * w.w;
    }
    int r0 = row0 + ty, r1 = row0 + ty + 16;
    if (r0 < n) {
        float d = g_dis[r0];
        g_h0h[r0 * 32 + tx * 2]     = __floats2half2_rn(a0.x * d, a0.y * d);
        g_h0h[r0 * 32 + tx * 2 + 1] = __floats2half2_rn(a0.z * d, a0.w * d);
    }
    if (r1 < n) {
        float d = g_dis[r1];
        g_h0h[r1 * 32 + tx * 2]     = __floats2half2_rn(a1.x * d, a1.y * d);
        g_h0h[r1 * 32 + tx * 2 + 1] = __floats2half2_rn(a1.z * d, a1.w * d);
    }
}

// ---------------- fused layer-1 aggregation + GEMM2 (MLP=8) ------------------
__global__ __launch_bounds__(256) void k_agg64_gemm2(const float* __restrict__ b1,
                                                     const float* __restrict__ Wmu,
                                                     const float* __restrict__ Wls,
                                                     int n) {
    __shared__ float hs[8][HID];     // 2 KB
    __shared__ float Wc[HID][32];    // 8 KB: cols 0..15 = W_mu, 16..31 = W_ls
    int tid  = threadIdx.x;
    int warp = tid >> 5, lane = tid & 31;
    for (int i = tid; i < HID * OUTC; i += 256) {
        int k = i >> 4, c = i & 15;
        Wc[k][c]      = Wmu[i];
        Wc[k][16 + c] = Wls[i];
    }
    int node = blockIdx.x * 8 + warp;
    if (node < n) {
        float2 acc = __half22float2(g_h0h[node * 32 + lane]);  // self (pre-scaled)
        int k   = g_off[node];
        int end = k + g_degi[node];
        for (; k + 7 < end; k += 8) {
            int s0 = g_csr[k],     s1 = g_csr[k + 1];
            int s2 = g_csr[k + 2], s3 = g_csr[k + 3];
            int s4 = g_csr[k + 4], s5 = g_csr[k + 5];
            int s6 = g_csr[k + 6], s7 = g_csr[k + 7];
            __half2 h0 = g_h0h[s0 * 32 + lane];
            __half2 h1 = g_h0h[s1 * 32 + lane];
            __half2 h2 = g_h0h[s2 * 32 + lane];
            __half2 h3 = g_h0h[s3 * 32 + lane];
            __half2 h4 = g_h0h[s4 * 32 + lane];
            __half2 h5 = g_h0h[s5 * 32 + lane];
            __half2 h6 = g_h0h[s6 * 32 + lane];
            __half2 h7 = g_h0h[s7 * 32 + lane];
            float2 a0 = __half22float2(h0), a1 = __half22float2(h1);
            float2 a2 = __half22float2(h2), a3 = __half22float2(h3);
            float2 a4 = __half22float2(h4), a5 = __half22float2(h5);
            float2 a6 = __half22float2(h6), a7 = __half22float2(h7);
            acc.x += (a0.x + a1.x) + (a2.x + a3.x) + ((a4.x + a5.x) + (a6.x + a7.x));
            acc.y += (a0.y + a1.y) + (a2.y + a3.y) + ((a4.y + a5.y) + (a6.y + a7.y));
        }
        for (; k + 3 < end; k += 4) {
            int s0 = g_csr[k],     s1 = g_csr[k + 1];
            int s2 = g_csr[k + 2], s3 = g_csr[k + 3];
            float2 a0 = __half22float2(g_h0h[s0 * 32 + lane]);
            float2 a1 = __half22float2(g_h0h[s1 * 32 + lane]);
            float2 a2 = __half22float2(g_h0h[s2 * 32 + lane]);
            float2 a3 = __half22float2(g_h0h[s3 * 32 + lane]);
            acc.x += (a0.x + a1.x) + (a2.x + a3.x);
            acc.y += (a0.y + a1.y) + (a2.y + a3.y);
        }
        for (; k < end; k++) {
            float2 a0 = __half22float2(g_h0h[g_csr[k] * 32 + lane]);
            acc.x += a0.x; acc.y += a0.y;
        }
        float d = g_dis[node];
        int c2 = lane * 2;
        float2 bb = *(const float2*)&b1[c2];
        hs[warp][c2]     = fmaxf(acc.x * d + bb.x, 0.f);
        hs[warp][c2 + 1] = fmaxf(acc.y * d + bb.y, 0.f);
    }
    __syncthreads();
    if (node < n) {
        float s0 = 0.f, s1 = 0.f;
        #pragma unroll
        for (int k = 0; k < HID; k++) {
            float hv = hs[warp][k];
            s0 += hv * Wc[k][(lane & 15) * 2];
            s1 += hv * Wc[k][(lane & 15) * 2 + 1];
        }
        if (lane < 16) {
            float d = g_dis[node];
            g_zh[node * 16 + lane] = __floats2half2_rn(s0 * d, s1 * d);
        }
    }
}

// ---------------- layer-2 aggregation (16-lane subwarp/node, MLP=8) ----------
__global__ __launch_bounds__(256) void k_agg32(const float* __restrict__ bmu,
                                               const float* __restrict__ bls,
                                               float* __restrict__ out, int n) {
    int tid  = threadIdx.x;
    int node = blockIdx.x * 16 + (tid >> 4);
    if (node >= n) return;
    int li = tid & 15;
    float2 acc = __half22float2(g_zh[node * 16 + li]);
    int k   = g_off[node];
    int end = k + g_degi[node];
    for (; k + 7 < end; k += 8) {
        int s0 = g_csr[k],     s1 = g_csr[k + 1];
        int s2 = g_csr[k + 2], s3 = g_csr[k + 3];
        int s4 = g_csr[k + 4], s5 = g_csr[k + 5];
        int s6 = g_csr[k + 6], s7 = g_csr[k + 7];
        __half2 h0 = g_zh[s0 * 16 + li];
        __half2 h1 = g_zh[s1 * 16 + li];
        __half2 h2 = g_zh[s2 * 16 + li];
        __half2 h3 = g_zh[s3 * 16 + li];
        __half2 h4 = g_zh[s4 * 16 + li];
        __half2 h5 = g_zh[s5 * 16 + li];
        __half2 h6 = g_zh[s6 * 16 + li];
        __half2 h7 = g_zh[s7 * 16 + li];
        float2 a0 = __half22float2(h0), a1 = __half22float2(h1);
        float2 a2 = __half22float2(h2), a3 = __half22float2(h3);
        float2 a4 = __half22float2(h4), a5 = __half22float2(h5);
        float2 a6 = __half22float2(h6), a7 = __half22float2(h7);
        acc.x += (a0.x + a1.x) + (a2.x + a3.x) + ((a4.x + a5.x) + (a6.x + a7.x));
        acc.y += (a0.y + a1.y) + (a2.y + a3.y) + ((a4.y + a5.y) + (a6.y + a7.y));
    }
    for (; k + 3 < end; k += 4) {
        int s0 = g_csr[k],     s1 = g_csr[k + 1];
        int s2 = g_csr[k + 2], s3 = g_csr[k + 3];
        float2 a0 = __half22float2(g_zh[s0 * 16 + li]);
        float2 a1 = __half22float2(g_zh[s1 * 16 + li]);
        float2 a2 = __half22float2(g_zh[s2 * 16 + li]);
        float2 a3 = __half22float2(g_zh[s3 * 16 + li]);
        acc.x += (a0.x + a1.x) + (a2.x + a3.x);
        acc.y += (a0.y + a1.y) + (a2.y + a3.y);
    }
    for (; k < end; k++) {
        float2 a0 = __half22float2(g_zh[g_csr[k] * 16 + li]);
        acc.x += a0.x; acc.y += a0.y;
    }
    float d = g_dis[node];
    int c2 = li * 2;
    float2 r;
    if (c2 < 16) {
        const float2 bb = *(const float2*)&bmu[c2];
        r.x = acc.x * d + bb.x; r.y = acc.y * d + bb.y;
        *(float2*)&out[node * 16 + c2] = r;
    } else {
        const float2 bb = *(const float2*)&bls[c2 - 16];
        r.x = acc.x * d + bb.x; r.y = acc.y * d + bb.y;
        *(float2*)&out[n * 16 + node * 16 + (c2 - 16)] = r;
    }
}

// ---------------- launch ------------------------------------------------------
extern "C" void kernel_launch(void* const* d_in, const int* in_sizes, int n_in,
                              void* d_out, int out_size) {
    const float* x   = (const float*)d_in[0];
    const void*  eix = d_in[1];
    const float* W1  = (const float*)d_in[2];
    const float* b1  = (const float*)d_in[3];
    const float* Wmu = (const float*)d_in[4];
    const float* bmu = (const float*)d_in[5];
    const float* Wls = (const float*)d_in[6];
    const float* bls = (const float*)d_in[7];
    float* out = (float*)d_out;

    int n = in_sizes[0] / INC;      // 100000
    int E = in_sizes[1] / 2;        // 3200000
    int nb = (n + 255) / 256;

    k_detect<<<1, 1>>>((const int*)eix);
    k_zero_deg<<<nb, 256>>>(n);
    k_conv_count<<<(E + 255) / 256, 256>>>(eix, E);

    k_scan1<<<nb, 256>>>(n);
    k_scan2<<<1, 1024>>>(nb);
    k_scan3<<<nb, 256>>>(n);
    k_scatter<<<(E + 255) / 256, 256>>>(eix, E);

    k_gemm1<<<(n + 31) / 32, dim3(16, 16)>>>(x, W1, n);
    k_agg64_gemm2<<<(n + 7) / 8, 256>>>(b1, Wmu, Wls, n);
    k_agg32<<<(n + 15) / 16, 256>>>(bmu, bls, out, n);
}

// round 9
// speedup vs baseline: 1.1957x; 1.0554x over previous
#include <cuda_runtime.h>
#include <cuda_fp16.h>
#include <cstdint>

#define NN   100000
#define EE   3200000
#define INC  128
#define HID  64
#define OUTC 16

// ---------------- scratch (static device globals; no allocation) -------------
__device__ __half2 g_h0h[NN * 32];    // (x @ W1) * dis[row], fp16, 64ch (32 half2)
__device__ __half2 g_zh[NN * 16];     // (relu(agg1) @ [Wmu|Wls]) * dis[row], 32ch
__device__ float g_dis[NN];           // (deg+1)^-1/2
__device__ int   g_csr[EE];           // src indices sorted by dst
__device__ int   g_degi[NN];
__device__ int   g_offA[NN];
__device__ int   g_off[NN];
__device__ int   g_woff[NN];
__device__ int   g_bsum[1024];
__device__ int   g_bpre[1024];
__device__ int   g_is64;

// ---------------- stream/event resources (created at load, before checkpoint)-
namespace {
struct Resources {
    cudaStream_t s2;
    cudaEvent_t  ev_fork, ev_join;
    Resources() {
        cudaStreamCreateWithFlags(&s2, cudaStreamNonBlocking);
        cudaEventCreateWithFlags(&ev_fork, cudaEventDisableTiming);
        cudaEventCreateWithFlags(&ev_join, cudaEventDisableTiming);
    }
};
Resources g_res;
}

// ---------------- dtype detection -------------------------------------------
__global__ void k_detect(const int* e) {
    int all_zero = 1;
    #pragma unroll
    for (int i = 1; i < 129; i += 2)
        if (e[i] != 0) { all_zero = 0; break; }
    g_is64 = all_zero;
}

__global__ void k_zero_deg(int n) {
    int i = blockIdx.x * blockDim.x + threadIdx.x;
    if (i < n) g_degi[i] = 0;
}

// count in-degree straight from the dst half of the edge buffer
__global__ void k_conv_count(const void* eidx, int E) {
    int i = blockIdx.x * blockDim.x + threadIdx.x;
    if (i >= E) return;
    int v;
    if (g_is64) v = (int)((const long long*)eidx)[E + i];
    else        v = ((const int*)eidx)[E + i];
    atomicAdd(&g_degi[v], 1);
}

// ---------------- hierarchical exclusive scan of degrees ---------------------
__global__ void k_scan1(int n) {
    __shared__ int s[256];
    int i = blockIdx.x * 256 + threadIdx.x;
    int v = (i < n) ? g_degi[i] : 0;
    s[threadIdx.x] = v;
    __syncthreads();
    #pragma unroll
    for (int off = 1; off < 256; off <<= 1) {
        int t = (threadIdx.x >= off) ? s[threadIdx.x - off] : 0;
        __syncthreads();
        s[threadIdx.x] += t;
        __syncthreads();
    }
    if (i < n) g_offA[i] = s[threadIdx.x] - v;
    if (threadIdx.x == 255) g_bsum[blockIdx.x] = s[255];
}

__global__ void k_scan2(int nb) {
    __shared__ int s[1024];
    int v = (threadIdx.x < nb) ? g_bsum[threadIdx.x] : 0;
    s[threadIdx.x] = v;
    __syncthreads();
    #pragma unroll
    for (int off = 1; off < 1024; off <<= 1) {
        int t = (threadIdx.x >= off) ? s[threadIdx.x - off] : 0;
        __syncthreads();
        s[threadIdx.x] += t;
        __syncthreads();
    }
    if (threadIdx.x < nb) g_bpre[threadIdx.x] = s[threadIdx.x] - v;
}

__global__ void k_scan3(int n) {
    int i = blockIdx.x * blockDim.x + threadIdx.x;
    if (i >= n) return;
    int o = g_offA[i] + g_bpre[i >> 8];
    g_off[i]  = o;
    g_woff[i] = o;
    g_dis[i]  = rsqrtf((float)(g_degi[i] + 1));
}

// ---------------- counting-sort scatter (converts src inline) ----------------
__global__ void k_scatter(const void* eidx, int E) {
    int e = blockIdx.x * blockDim.x + threadIdx.x;
    if (e >= E) return;
    int d, s;
    if (g_is64) {
        d = (int)((const long long*)eidx)[E + e];
        s = (int)((const long long*)eidx)[e];
    } else {
        d = ((const int*)eidx)[E + e];
        s = ((const int*)eidx)[e];
    }
    int pos = atomicAdd(&g_woff[d], 1);
    g_csr[pos] = s;
}

// ---------------- GEMM1: h0h = fp16( (x @ W1) * dis[row] ), 2 rows/thread ----
__global__ __launch_bounds__(256) void k_gemm1(const float* __restrict__ x,
                                               const float* __restrict__ W,
                                               int n) {
    __shared__ float Ws[INC][HID];    // 32 KB
    __shared__ float xs[32][INC];     // 16 KB
    int tx = threadIdx.x, ty = threadIdx.y;          // blockDim (16,16)
    int tid = ty * 16 + tx;
    for (int i = tid; i < INC * HID; i += 256)
        ((float*)Ws)[i] = W[i];
    int row0 = blockIdx.x * 32;
    for (int i = tid; i < 32 * INC; i += 256) {
        int r = i >> 7, k = i & 127;
        int row = row0 + r;
        xs[r][k] = (row < n) ? x[row * INC + k] : 0.f;
    }
    __syncthreads();

    float4 a0 = make_float4(0.f, 0.f, 0.f, 0.f);
    float4 a1 = make_float4(0.f, 0.f, 0.f, 0.f);
    #pragma unroll 4
    for (int k = 0; k < INC; k++) {
        float4 w = *(const float4*)&Ws[k][tx * 4];
        float v0 = xs[ty][k];
        float v1 = xs[ty + 16][k];
        a0.x += v0 * w.x; a0.y += v0 * w.y; a0.z += v0 * w.z; a0.w += v0 * w.w;
        a1.x += v1 * w.x; a1.y += v1 * w.y; a1.z += v1 * w.z; a1.w += v1 * w.w;
    }
    int r0 = row0 + ty, r1 = row0 + ty + 16;
    if (r0 < n) {
        float d = g_dis[r0];
        g_h0h[r0 * 32 + tx * 2]     = __floats2half2_rn(a0.x * d, a0.y * d);
        g_h0h[r0 * 32 + tx * 2 + 1] = __floats2half2_rn(a0.z * d, a0.w * d);
    }
    if (r1 < n) {
        float d = g_dis[r1];
        g_h0h[r1 * 32 + tx * 2]     = __floats2half2_rn(a1.x * d, a1.y * d);
        g_h0h[r1 * 32 + tx * 2 + 1] = __floats2half2_rn(a1.z * d, a1.w * d);
    }
}

// ---------------- fused layer-1 aggregation + GEMM2 (MLP=8) ------------------
__global__ __launch_bounds__(256) void k_agg64_gemm2(const float* __restrict__ b1,
                                                     const float* __restrict__ Wmu,
                                                     const float* __restrict__ Wls,
                                                     int n) {
    __shared__ float hs[8][HID];     // 2 KB
    __shared__ float Wc[HID][32];    // 8 KB: cols 0..15 = W_mu, 16..31 = W_ls
    int tid  = threadIdx.x;
    int warp = tid >> 5, lane = tid & 31;
    for (int i = tid; i < HID * OUTC; i += 256) {
        int k = i >> 4, c = i & 15;
        Wc[k][c]      = Wmu[i];
        Wc[k][16 + c] = Wls[i];
    }
    int node = blockIdx.x * 8 + warp;
    if (node < n) {
        float2 acc = __half22float2(g_h0h[node * 32 + lane]);  // self (pre-scaled)
        int k   = g_off[node];
        int end = k + g_degi[node];
        for (; k + 7 < end; k += 8) {
            int s0 = g_csr[k],     s1 = g_csr[k + 1];
            int s2 = g_csr[k + 2], s3 = g_csr[k + 3];
            int s4 = g_csr[k + 4], s5 = g_csr[k + 5];
            int s6 = g_csr[k + 6], s7 = g_csr[k + 7];
            __half2 h0 = g_h0h[s0 * 32 + lane];
            __half2 h1 = g_h0h[s1 * 32 + lane];
            __half2 h2 = g_h0h[s2 * 32 + lane];
            __half2 h3 = g_h0h[s3 * 32 + lane];
            __half2 h4 = g_h0h[s4 * 32 + lane];
            __half2 h5 = g_h0h[s5 * 32 + lane];
            __half2 h6 = g_h0h[s6 * 32 + lane];
            __half2 h7 = g_h0h[s7 * 32 + lane];
            float2 a0 = __half22float2(h0), a1 = __half22float2(h1);
            float2 a2 = __half22float2(h2), a3 = __half22float2(h3);
            float2 a4 = __half22float2(h4), a5 = __half22float2(h5);
            float2 a6 = __half22float2(h6), a7 = __half22float2(h7);
            acc.x += (a0.x + a1.x) + (a2.x + a3.x) + ((a4.x + a5.x) + (a6.x + a7.x));
            acc.y += (a0.y + a1.y) + (a2.y + a3.y) + ((a4.y + a5.y) + (a6.y + a7.y));
        }
        for (; k + 3 < end; k += 4) {
            int s0 = g_csr[k],     s1 = g_csr[k + 1];
            int s2 = g_csr[k + 2], s3 = g_csr[k + 3];
            float2 a0 = __half22float2(g_h0h[s0 * 32 + lane]);
            float2 a1 = __half22float2(g_h0h[s1 * 32 + lane]);
            float2 a2 = __half22float2(g_h0h[s2 * 32 + lane]);
            float2 a3 = __half22float2(g_h0h[s3 * 32 + lane]);
            acc.x += (a0.x + a1.x) + (a2.x + a3.x);
            acc.y += (a0.y + a1.y) + (a2.y + a3.y);
        }
        for (; k < end; k++) {
            float2 a0 = __half22float2(g_h0h[g_csr[k] * 32 + lane]);
            acc.x += a0.x; acc.y += a0.y;
        }
        float d = g_dis[node];
        int c2 = lane * 2;
        float2 bb = *(const float2*)&b1[c2];
        hs[warp][c2]     = fmaxf(acc.x * d + bb.x, 0.f);
        hs[warp][c2 + 1] = fmaxf(acc.y * d + bb.y, 0.f);
    }
    __syncthreads();
    if (node < n) {
        float s0 = 0.f, s1 = 0.f;
        #pragma unroll
        for (int k = 0; k < HID; k++) {
            float hv = hs[warp][k];
            s0 += hv * Wc[k][(lane & 15) * 2];
            s1 += hv * Wc[k][(lane & 15) * 2 + 1];
        }
        if (lane < 16) {
            float d = g_dis[node];
            g_zh[node * 16 + lane] = __floats2half2_rn(s0 * d, s1 * d);
        }
    }
}

// ---------------- layer-2 aggregation (16-lane subwarp/node, MLP=8) ----------
__global__ __launch_bounds__(256) void k_agg32(const float* __restrict__ bmu,
                                               const float* __restrict__ bls,
                                               float* __restrict__ out, int n) {
    int tid  = threadIdx.x;
    int node = blockIdx.x * 16 + (tid >> 4);
    if (node >= n) return;
    int li = tid & 15;
    float2 acc = __half22float2(g_zh[node * 16 + li]);
    int k   = g_off[node];
    int end = k + g_degi[node];
    for (; k + 7 < end; k += 8) {
        int s0 = g_csr[k],     s1 = g_csr[k + 1];
        int s2 = g_csr[k + 2], s3 = g_csr[k + 3];
        int s4 = g_csr[k + 4], s5 = g_csr[k + 5];
        int s6 = g_csr[k + 6], s7 = g_csr[k + 7];
        __half2 h0 = g_zh[s0 * 16 + li];
        __half2 h1 = g_zh[s1 * 16 + li];
        __half2 h2 = g_zh[s2 * 16 + li];
        __half2 h3 = g_zh[s3 * 16 + li];
        __half2 h4 = g_zh[s4 * 16 + li];
        __half2 h5 = g_zh[s5 * 16 + li];
        __half2 h6 = g_zh[s6 * 16 + li];
        __half2 h7 = g_zh[s7 * 16 + li];
        float2 a0 = __half22float2(h0), a1 = __half22float2(h1);
        float2 a2 = __half22float2(h2), a3 = __half22float2(h3);
        float2 a4 = __half22float2(h4), a5 = __half22float2(h5);
        float2 a6 = __half22float2(h6), a7 = __half22float2(h7);
        acc.x += (a0.x + a1.x) + (a2.x + a3.x) + ((a4.x + a5.x) + (a6.x + a7.x));
        acc.y += (a0.y + a1.y) + (a2.y + a3.y) + ((a4.y + a5.y) + (a6.y + a7.y));
    }
    for (; k + 3 < end; k += 4) {
        int s0 = g_csr[k],     s1 = g_csr[k + 1];
        int s2 = g_csr[k + 2], s3 = g_csr[k + 3];
        float2 a0 = __half22float2(g_zh[s0 * 16 + li]);
        float2 a1 = __half22float2(g_zh[s1 * 16 + li]);
        float2 a2 = __half22float2(g_zh[s2 * 16 + li]);
        float2 a3 = __half22float2(g_zh[s3 * 16 + li]);
        acc.x += (a0.x + a1.x) + (a2.x + a3.x);
        acc.y += (a0.y + a1.y) + (a2.y + a3.y);
    }
    for (; k < end; k++) {
        float2 a0 = __half22float2(g_zh[g_csr[k] * 16 + li]);
        acc.x += a0.x; acc.y += a0.y;
    }
    float d = g_dis[node];
    int c2 = li * 2;
    float2 r;
    if (c2 < 16) {
        const float2 bb = *(const float2*)&bmu[c2];
        r.x = acc.x * d + bb.x; r.y = acc.y * d + bb.y;
        *(float2*)&out[node * 16 + c2] = r;
    } else {
        const float2 bb = *(const float2*)&bls[c2 - 16];
        r.x = acc.x * d + bb.x; r.y = acc.y * d + bb.y;
        *(float2*)&out[n * 16 + node * 16 + (c2 - 16)] = r;
    }
}

// ---------------- launch ------------------------------------------------------
extern "C" void kernel_launch(void* const* d_in, const int* in_sizes, int n_in,
                              void* d_out, int out_size) {
    const float* x   = (const float*)d_in[0];
    const void*  eix = d_in[1];
    const float* W1  = (const float*)d_in[2];
    const float* b1  = (const float*)d_in[3];
    const float* Wmu = (const float*)d_in[4];
    const float* bmu = (const float*)d_in[5];
    const float* Wls = (const float*)d_in[6];
    const float* bls = (const float*)d_in[7];
    float* out = (float*)d_out;

    int n = in_sizes[0] / INC;      // 100000
    int E = in_sizes[1] / 2;        // 3200000
    int nb = (n + 255) / 256;

    k_detect<<<1, 1>>>((const int*)eix);
    k_zero_deg<<<nb, 256>>>(n);
    k_conv_count<<<(E + 255) / 256, 256>>>(eix, E);

    k_scan1<<<nb, 256>>>(n);
    k_scan2<<<1, 1024>>>(nb);
    k_scan3<<<nb, 256>>>(n);

    // fork: gemm1 (needs only g_dis) runs on s2 concurrently with scatter
    cudaEventRecord(g_res.ev_fork, 0);
    cudaStreamWaitEvent(g_res.s2, g_res.ev_fork, 0);
    k_gemm1<<<(n + 31) / 32, dim3(16, 16), 0, g_res.s2>>>(x, W1, n);
    cudaEventRecord(g_res.ev_join, g_res.s2);

    k_scatter<<<(E + 255) / 256, 256>>>(eix, E);

    // join: agg64 needs both csr (default stream) and h0h (s2)
    cudaStreamWaitEvent(0, g_res.ev_join, 0);
    k_agg64_gemm2<<<(n + 7) / 8, 256>>>(b1, Wmu, Wls, n);
    k_agg32<<<(n + 15) / 16, 256>>>(bmu, bls, out, n);
}

// round 10
// speedup vs baseline: 1.2062x; 1.0087x over previous
#include <cuda_runtime.h>
#include <cuda_fp16.h>
#include <cstdint>

#define NN   100000
#define EE   3200000
#define INC  128
#define HID  64
#define OUTC 16

// ---------------- scratch (static device globals; no allocation) -------------
__device__ float   g_h0f[NN * HID];   // x @ W1 (fp32, unscaled)
__device__ __half2 g_h0h[NN * 32];    // (x @ W1) * dis[row], fp16, 64ch
__device__ __half2 g_zh[NN * 16];     // (relu(agg1) @ [Wmu|Wls]) * dis[row], 32ch
__device__ float g_dis[NN];           // (deg+1)^-1/2
__device__ int   g_csr[EE];           // src indices sorted by dst
__device__ int   g_degi[NN];
__device__ int   g_offA[NN];
__device__ int   g_off[NN];
__device__ int   g_woff[NN];
__device__ int   g_bsum[1024];
__device__ int   g_bpre[1024];
__device__ int   g_is64;

// ---------------- stream/event resources (created at load, before checkpoint)-
namespace {
struct Resources {
    cudaStream_t s2;
    cudaEvent_t  ev_fork, ev_scan, ev_join;
    Resources() {
        cudaStreamCreateWithFlags(&s2, cudaStreamNonBlocking);
        cudaEventCreateWithFlags(&ev_fork, cudaEventDisableTiming);
        cudaEventCreateWithFlags(&ev_scan, cudaEventDisableTiming);
        cudaEventCreateWithFlags(&ev_join, cudaEventDisableTiming);
    }
};
Resources g_res;
}

// ---------------- zero degrees + dtype detection ------------------------------
__global__ void k_zero_detect(const int* e, int n) {
    int i = blockIdx.x * blockDim.x + threadIdx.x;
    if (i < n) g_degi[i] = 0;
    if (i == 0) {
        int all_zero = 1;
        #pragma unroll
        for (int j = 1; j < 129; j += 2)
            if (e[j] != 0) { all_zero = 0; break; }
        g_is64 = all_zero;
    }
}

// count in-degree straight from the dst half of the edge buffer
__global__ void k_conv_count(const void* eidx, int E) {
    int i = blockIdx.x * blockDim.x + threadIdx.x;
    if (i >= E) return;
    int v;
    if (g_is64) v = (int)((const long long*)eidx)[E + i];
    else        v = ((const int*)eidx)[E + i];
    atomicAdd(&g_degi[v], 1);
}

// ---------------- hierarchical exclusive scan of degrees ---------------------
__global__ void k_scan1(int n) {
    __shared__ int s[256];
    int i = blockIdx.x * 256 + threadIdx.x;
    int v = (i < n) ? g_degi[i] : 0;
    s[threadIdx.x] = v;
    __syncthreads();
    #pragma unroll
    for (int off = 1; off < 256; off <<= 1) {
        int t = (threadIdx.x >= off) ? s[threadIdx.x - off] : 0;
        __syncthreads();
        s[threadIdx.x] += t;
        __syncthreads();
    }
    if (i < n) g_offA[i] = s[threadIdx.x] - v;
    if (threadIdx.x == 255) g_bsum[blockIdx.x] = s[255];
}

__global__ void k_scan2(int nb) {
    __shared__ int s[1024];
    int v = (threadIdx.x < nb) ? g_bsum[threadIdx.x] : 0;
    s[threadIdx.x] = v;
    __syncthreads();
    #pragma unroll
    for (int off = 1; off < 1024; off <<= 1) {
        int t = (threadIdx.x >= off) ? s[threadIdx.x - off] : 0;
        __syncthreads();
        s[threadIdx.x] += t;
        __syncthreads();
    }
    if (threadIdx.x < nb) g_bpre[threadIdx.x] = s[threadIdx.x] - v;
}

__global__ void k_scan3(int n) {
    int i = blockIdx.x * blockDim.x + threadIdx.x;
    if (i >= n) return;
    int o = g_offA[i] + g_bpre[i >> 8];
    g_off[i]  = o;
    g_woff[i] = o;
    g_dis[i]  = rsqrtf((float)(g_degi[i] + 1));
}

// ---------------- counting-sort scatter (converts src inline) ----------------
__global__ void k_scatter(const void* eidx, int E) {
    int e = blockIdx.x * blockDim.x + threadIdx.x;
    if (e >= E) return;
    int d, s;
    if (g_is64) {
        d = (int)((const long long*)eidx)[E + e];
        s = (int)((const long long*)eidx)[e];
    } else {
        d = ((const int*)eidx)[E + e];
        s = ((const int*)eidx)[e];
    }
    int pos = atomicAdd(&g_woff[d], 1);
    g_csr[pos] = s;
}

// ---------------- GEMM1 (fp32, no dis scale — runs at t=0 on s2) -------------
__global__ __launch_bounds__(256) void k_gemm1f(const float* __restrict__ x,
                                                const float* __restrict__ W,
                                                int n) {
    __shared__ float Ws[INC][HID];    // 32 KB
    __shared__ float xs[32][INC];     // 16 KB
    int tx = threadIdx.x, ty = threadIdx.y;          // blockDim (16,16)
    int tid = ty * 16 + tx;
    for (int i = tid; i < INC * HID; i += 256)
        ((float*)Ws)[i] = W[i];
    int row0 = blockIdx.x * 32;
    for (int i = tid; i < 32 * INC; i += 256) {
        int r = i >> 7, k = i & 127;
        int row = row0 + r;
        xs[r][k] = (row < n) ? x[row * INC + k] : 0.f;
    }
    __syncthreads();

    float4 a0 = make_float4(0.f, 0.f, 0.f, 0.f);
    float4 a1 = make_float4(0.f, 0.f, 0.f, 0.f);
    #pragma unroll 4
    for (int k = 0; k < INC; k++) {
        float4 w = *(const float4*)&Ws[k][tx * 4];
        float v0 = xs[ty][k];
        float v1 = xs[ty + 16][k];
        a0.x += v0 * w.x; a0.y += v0 * w.y; a0.z += v0 * w.z; a0.w += v0 * w.w;
        a1.x += v1 * w.x; a1.y += v1 * w.y; a1.z += v1 * w.z; a1.w += v1 * w.w;
    }
    int r0 = row0 + ty, r1 = row0 + ty + 16;
    if (r0 < n) *(float4*)&g_h0f[r0 * HID + tx * 4] = a0;
    if (r1 < n) *(float4*)&g_h0f[r1 * HID + tx * 4] = a1;
}

// ---------------- scale h0f by dis[row], convert to fp16 ---------------------
__global__ void k_scale(int n) {
    int idx = blockIdx.x * blockDim.x + threadIdx.x;   // n*32 half2 slots
    if (idx >= n * 32) return;
    int node = idx >> 5;
    float d = g_dis[node];
    float2 v = *(const float2*)&g_h0f[idx * 2];
    g_h0h[idx] = __floats2half2_rn(v.x * d, v.y * d);
}

// ---------------- fused layer-1 aggregation + GEMM2 --------------------------
// One warp per node. HADD2 pair-reduce + int4 index loads, fp32 accumulate.
__global__ __launch_bounds__(256) void k_agg64_gemm2(const float* __restrict__ b1,
                                                     const float* __restrict__ Wmu,
                                                     const float* __restrict__ Wls,
                                                     int n) {
    __shared__ float hs[8][HID];     // 2 KB
    __shared__ float Wc[HID][32];    // 8 KB: cols 0..15 = W_mu, 16..31 = W_ls
    int tid  = threadIdx.x;
    int warp = tid >> 5, lane = tid & 31;
    for (int i = tid; i < HID * OUTC; i += 256) {
        int k = i >> 4, c = i & 15;
        Wc[k][c]      = Wmu[i];
        Wc[k][16 + c] = Wls[i];
    }
    int node = blockIdx.x * 8 + warp;
    if (node < n) {
        float2 acc = __half22float2(g_h0h[node * 32 + lane]);  // self (pre-scaled)
        int k   = g_off[node];
        int end = k + g_degi[node];
        // peel to 16B alignment of &g_csr[k]
        while (k < end && (k & 3)) {
            float2 a0 = __half22float2(g_h0h[g_csr[k] * 32 + lane]);
            acc.x += a0.x; acc.y += a0.y;
            k++;
        }
        for (; k + 7 < end; k += 8) {
            int4 i0 = *(const int4*)&g_csr[k];
            int4 i1 = *(const int4*)&g_csr[k + 4];
            __half2 h0 = g_h0h[i0.x * 32 + lane];
            __half2 h1 = g_h0h[i0.y * 32 + lane];
            __half2 h2 = g_h0h[i0.z * 32 + lane];
            __half2 h3 = g_h0h[i0.w * 32 + lane];
            __half2 h4 = g_h0h[i1.x * 32 + lane];
            __half2 h5 = g_h0h[i1.y * 32 + lane];
            __half2 h6 = g_h0h[i1.z * 32 + lane];
            __half2 h7 = g_h0h[i1.w * 32 + lane];
            __half2 p0 = __hadd2(h0, h1);
            __half2 p1 = __hadd2(h2, h3);
            __half2 p2 = __hadd2(h4, h5);
            __half2 p3 = __hadd2(h6, h7);
            float2 a0 = __half22float2(p0), a1 = __half22float2(p1);
            float2 a2 = __half22float2(p2), a3 = __half22float2(p3);
            acc.x += (a0.x + a1.x) + (a2.x + a3.x);
            acc.y += (a0.y + a1.y) + (a2.y + a3.y);
        }
        if (k + 3 < end) {
            int4 i0 = *(const int4*)&g_csr[k];
            __half2 h0 = g_h0h[i0.x * 32 + lane];
            __half2 h1 = g_h0h[i0.y * 32 + lane];
            __half2 h2 = g_h0h[i0.z * 32 + lane];
            __half2 h3 = g_h0h[i0.w * 32 + lane];
            __half2 p0 = __hadd2(h0, h1);
            __half2 p1 = __hadd2(h2, h3);
            float2 a0 = __half22float2(p0), a1 = __half22float2(p1);
            acc.x += a0.x + a1.x;
            acc.y += a0.y + a1.y;
            k += 4;
        }
        for (; k < end; k++) {
            float2 a0 = __half22float2(g_h0h[g_csr[k] * 32 + lane]);
            acc.x += a0.x; acc.y += a0.y;
        }
        float d = g_dis[node];
        int c2 = lane * 2;
        float2 bb = *(const float2*)&b1[c2];
        hs[warp][c2]     = fmaxf(acc.x * d + bb.x, 0.f);
        hs[warp][c2 + 1] = fmaxf(acc.y * d + bb.y, 0.f);
    }
    __syncthreads();
    if (node < n) {
        float s0 = 0.f, s1 = 0.f;
        #pragma unroll
        for (int k = 0; k < HID; k++) {
            float hv = hs[warp][k];
            s0 += hv * Wc[k][(lane & 15) * 2];
            s1 += hv * Wc[k][(lane & 15) * 2 + 1];
        }
        if (lane < 16) {
            float d = g_dis[node];
            g_zh[node * 16 + lane] = __floats2half2_rn(s0 * d, s1 * d);
        }
    }
}

// ---------------- layer-2 aggregation (16-lane subwarp/node) -----------------
__global__ __launch_bounds__(256) void k_agg32(const float* __restrict__ bmu,
                                               const float* __restrict__ bls,
                                               float* __restrict__ out, int n) {
    int tid  = threadIdx.x;
    int node = blockIdx.x * 16 + (tid >> 4);
    if (node >= n) return;
    int li = tid & 15;
    float2 acc = __half22float2(g_zh[node * 16 + li]);
    int k   = g_off[node];
    int end = k + g_degi[node];
    while (k < end && (k & 3)) {
        float2 a0 = __half22float2(g_zh[g_csr[k] * 16 + li]);
        acc.x += a0.x; acc.y += a0.y;
        k++;
    }
    for (; k + 7 < end; k += 8) {
        int4 i0 = *(const int4*)&g_csr[k];
        int4 i1 = *(const int4*)&g_csr[k + 4];
        __half2 h0 = g_zh[i0.x * 16 + li];
        __half2 h1 = g_zh[i0.y * 16 + li];
        __half2 h2 = g_zh[i0.z * 16 + li];
        __half2 h3 = g_zh[i0.w * 16 + li];
        __half2 h4 = g_zh[i1.x * 16 + li];
        __half2 h5 = g_zh[i1.y * 16 + li];
        __half2 h6 = g_zh[i1.z * 16 + li];
        __half2 h7 = g_zh[i1.w * 16 + li];
        __half2 p0 = __hadd2(h0, h1);
        __half2 p1 = __hadd2(h2, h3);
        __half2 p2 = __hadd2(h4, h5);
        __half2 p3 = __hadd2(h6, h7);
        float2 a0 = __half22float2(p0), a1 = __half22float2(p1);
        float2 a2 = __half22float2(p2), a3 = __half22float2(p3);
        acc.x += (a0.x + a1.x) + (a2.x + a3.x);
        acc.y += (a0.y + a1.y) + (a2.y + a3.y);
    }
    if (k + 3 < end) {
        int4 i0 = *(const int4*)&g_csr[k];
        __half2 h0 = g_zh[i0.x * 16 + li];
        __half2 h1 = g_zh[i0.y * 16 + li];
        __half2 h2 = g_zh[i0.z * 16 + li];
        __half2 h3 = g_zh[i0.w * 16 + li];
        __half2 p0 = __hadd2(h0, h1);
        __half2 p1 = __hadd2(h2, h3);
        float2 a0 = __half22float2(p0), a1 = __half22float2(p1);
        acc.x += a0.x + a1.x;
        acc.y += a0.y + a1.y;
        k += 4;
    }
    for (; k < end; k++) {
        float2 a0 = __half22float2(g_zh[g_csr[k] * 16 + li]);
        acc.x += a0.x; acc.y += a0.y;
    }
    float d = g_dis[node];
    int c2 = li * 2;
    float2 r;
    if (c2 < 16) {
        const float2 bb = *(const float2*)&bmu[c2];
        r.x = acc.x * d + bb.x; r.y = acc.y * d + bb.y;
        *(float2*)&out[node * 16 + c2] = r;
    } else {
        const float2 bb = *(const float2*)&bls[c2 - 16];
        r.x = acc.x * d + bb.x; r.y = acc.y * d + bb.y;
        *(float2*)&out[n * 16 + node * 16 + (c2 - 16)] = r;
    }
}

// ---------------- launch ------------------------------------------------------
extern "C" void kernel_launch(void* const* d_in, const int* in_sizes, int n_in,
                              void* d_out, int out_size) {
    const float* x   = (const float*)d_in[0];
    const void*  eix = d_in[1];
    const float* W1  = (const float*)d_in[2];
    const float* b1  = (const float*)d_in[3];
    const float* Wmu = (const float*)d_in[4];
    const float* bmu = (const float*)d_in[5];
    const float* Wls = (const float*)d_in[6];
    const float* bls = (const float*)d_in[7];
    float* out = (float*)d_out;

    int n = in_sizes[0] / INC;      // 100000
    int E = in_sizes[1] / 2;        // 3200000
    int nb = (n + 255) / 256;

    // fork s2 immediately: gemm1f depends on nothing but x, W1
    cudaEventRecord(g_res.ev_fork, 0);
    cudaStreamWaitEvent(g_res.s2, g_res.ev_fork, 0);
    k_gemm1f<<<(n + 31) / 32, dim3(16, 16), 0, g_res.s2>>>(x, W1, n);

    k_zero_detect<<<nb, 256>>>((const int*)eix, n);
    k_conv_count<<<(E + 255) / 256, 256>>>(eix, E);
    k_scan1<<<nb, 256>>>(n);
    k_scan2<<<1, 1024>>>(nb);
    k_scan3<<<nb, 256>>>(n);

    // s2: scale+convert needs gemm1f (s2 order) and g_dis (scan3)
    cudaEventRecord(g_res.ev_scan, 0);
    cudaStreamWaitEvent(g_res.s2, g_res.ev_scan, 0);
    k_scale<<<(n * 32 + 255) / 256, 256, 0, g_res.s2>>>(n);
    cudaEventRecord(g_res.ev_join, g_res.s2);

    // default: scatter runs concurrently with k_scale
    k_scatter<<<(E + 255) / 256, 256>>>(eix, E);

    cudaStreamWaitEvent(0, g_res.ev_join, 0);
    k_agg64_gemm2<<<(n + 7) / 8, 256>>>(b1, Wmu, Wls, n);
    k_agg32<<<(n + 15) / 16, 256>>>(bmu, bls, out, n);
}